// round 2
// baseline (speedup 1.0000x reference)
#include <cuda_runtime.h>

#define TS   32          // output tile (TS x TS)
#define HALO 5
#define IN   42          // TS + 2*HALO
#define INS  44          // padded smem row stride for input arrays
#define IMH  512
#define IMW  512
#define NPLANES (32*3)
#define NPIX    ((long long)NPLANES * IMH * IMW)   // 25165824

// Normalized 11-tap Gaussian (sigma=1.5), compile-time so taps become FFMA-imm.
__device__ constexpr float GW[11] = {
    0.00102838f, 0.00759876f, 0.03600077f, 0.10936071f, 0.21300550f,
    0.26601172f,
    0.21300550f, 0.10936071f, 0.03600077f, 0.00759876f, 0.00102838f
};

__device__ double g_acc[2];   // [0] = sum |x-y|, [1] = sum ssim_map

__global__ void zero_acc_kernel() {
    g_acc[0] = 0.0;
    g_acc[1] = 0.0;
}

__global__ __launch_bounds__(256) void ssim_l1_kernel(
    const float* __restrict__ pred, const float* __restrict__ tgt)
{
    extern __shared__ float sm[];
    float* sX  = sm;                   // IN*INS each
    float* sY  = sX  + IN * INS;
    float* sXX = sY  + IN * INS;
    float* sYY = sXX + IN * INS;
    float* sXY = sYY + IN * INS;
    float* hX  = sXY + IN * INS;       // IN*TS each (H-pass results)
    float* hY  = hX  + IN * TS;
    float* hXX = hY  + IN * TS;
    float* hYY = hXX + IN * TS;
    float* hXY = hYY + IN * TS;

    const int tid = threadIdx.x;
    const int plane = blockIdx.z;
    const float* __restrict__ px = pred + (size_t)plane * (IMH * IMW);
    const float* __restrict__ py = tgt  + (size_t)plane * (IMH * IMW);
    const int bx0 = blockIdx.x * TS - HALO;
    const int by0 = blockIdx.y * TS - HALO;

    // ---- Load halo tile; compute products once per element; fold L1 for
    //      interior pixels (each image pixel is interior of exactly one tile).
    float l1 = 0.f;
    for (int i = tid; i < IN * IN; i += 256) {
        int r = i / IN;
        int c = i - r * IN;
        int gy = by0 + r, gx = bx0 + c;
        float x = 0.f, y = 0.f;
        if ((unsigned)gy < IMH && (unsigned)gx < IMW) {
            int o = gy * IMW + gx;
            x = px[o];
            y = py[o];
        }
        int s = r * INS + c;
        sX[s]  = x;      sY[s]  = y;
        sXX[s] = x * x;  sYY[s] = y * y;  sXY[s] = x * y;
        if (r >= HALO && r < IN - HALO && c >= HALO && c < IN - HALO)
            l1 += fabsf(x - y);
    }
    __syncthreads();

    // ---- Horizontal pass: 42 rows x 32 cols. Warp lanes = consecutive cols
    //      -> conflict-free LDS; all taps are FFMA-imm.
    for (int i = tid; i < IN * TS; i += 256) {
        int r = i >> 5;
        int c = i & (TS - 1);
        int b = r * INS + c;
        float ax = 0.f, ay = 0.f, axx = 0.f, ayy = 0.f, axy = 0.f;
#pragma unroll
        for (int k = 0; k < 11; k++) {
            float w = GW[k];
            ax  += w * sX [b + k];
            ay  += w * sY [b + k];
            axx += w * sXX[b + k];
            ayy += w * sYY[b + k];
            axy += w * sXY[b + k];
        }
        hX[i] = ax; hY[i] = ay; hXX[i] = axx; hYY[i] = ayy; hXY[i] = axy;
    }
    __syncthreads();

    // ---- Vertical pass + SSIM map. h row stride = 32 -> h[r+k][c] = i + 32k.
    float ssim = 0.f;
    for (int i = tid; i < TS * TS; i += 256) {
        float mu1 = 0.f, mu2 = 0.f, ex2 = 0.f, ey2 = 0.f, exy = 0.f;
#pragma unroll
        for (int k = 0; k < 11; k++) {
            int o = i + k * TS;
            float w = GW[k];
            mu1 += w * hX [o];
            mu2 += w * hY [o];
            ex2 += w * hXX[o];
            ey2 += w * hYY[o];
            exy += w * hXY[o];
        }
        float m11 = mu1 * mu1;
        float m22 = mu2 * mu2;
        float m12 = mu1 * mu2;
        float s1  = ex2 - m11;
        float s2  = ey2 - m22;
        float s12 = exy - m12;
        const float C1 = 1e-4f;   // 0.01^2
        const float C2 = 9e-4f;   // 0.03^2
        float num = (2.f * m12 + C1) * (2.f * s12 + C2);
        float den = (m11 + m22 + C1) * (s1 + s2 + C2);
        ssim += __fdividef(num, den);
    }

    // ---- Block reduction of (l1, ssim), then one atomicAdd pair per block.
#pragma unroll
    for (int off = 16; off > 0; off >>= 1) {
        l1   += __shfl_down_sync(0xffffffffu, l1,   off);
        ssim += __shfl_down_sync(0xffffffffu, ssim, off);
    }
    int warp = tid >> 5;
    int lane = tid & 31;
    if (lane == 0) {            // sX region is dead after the 2nd barrier
        sX[warp]     = l1;
        sX[8 + warp] = ssim;
    }
    __syncthreads();
    if (tid == 0) {
        double a = 0.0, b = 0.0;
#pragma unroll
        for (int w = 0; w < 8; w++) { a += (double)sX[w]; b += (double)sX[8 + w]; }
        atomicAdd(&g_acc[0], a);
        atomicAdd(&g_acc[1], b);
    }
}

__global__ void finalize_kernel(float* __restrict__ out) {
    const double n = (double)NPIX;
    double l1 = g_acc[0] / n;
    double ss = g_acc[1] / n;
    out[0] = (float)(0.84 * l1 + (1.0 - 0.84) * (1.0 - ss));
}

extern "C" void kernel_launch(void* const* d_in, const int* in_sizes, int n_in,
                              void* d_out, int out_size)
{
    const float* pred = (const float*)d_in[0];
    const float* tgt  = (const float*)d_in[1];
    float* out = (float*)d_out;

    const int smem_bytes = (5 * IN * INS + 5 * IN * TS) * (int)sizeof(float); // 63840
    cudaFuncSetAttribute(ssim_l1_kernel,
                         cudaFuncAttributeMaxDynamicSharedMemorySize, smem_bytes);

    zero_acc_kernel<<<1, 1>>>();
    dim3 grid(IMW / TS, IMH / TS, NPLANES);   // 16 x 16 x 96
    ssim_l1_kernel<<<grid, 256, smem_bytes>>>(pred, tgt);
    finalize_kernel<<<1, 1>>>(out);
}

// round 4
// speedup vs baseline: 1.1463x; 1.1463x over previous
#include <cuda_runtime.h>

#define TS   32          // output tile (TS x TS)
#define HALO 5
#define IN   42          // TS + 2*HALO
#define INS  44          // padded smem row stride for input arrays (mult of 4)
#define IMH  512
#define IMW  512
#define NPLANES (32*3)
#define NPIX    ((long long)NPLANES * IMH * IMW)   // 25165824

// Normalized 11-tap Gaussian (sigma=1.5), compile-time so taps become FFMA-imm.
__device__ constexpr float GW[11] = {
    0.00102838f, 0.00759876f, 0.03600077f, 0.10936071f, 0.21300550f,
    0.26601172f,
    0.21300550f, 0.10936071f, 0.03600077f, 0.00759876f, 0.00102838f
};

__device__ double g_acc[2];   // [0] = sum |x-y|, [1] = sum ssim_map

__global__ void zero_acc_kernel() {
    g_acc[0] = 0.0;
    g_acc[1] = 0.0;
}

// Sliding-window horizontal conv: 16 inputs -> 4 outputs (cols j..j+3).
__device__ __forceinline__ void hconv4(const float* __restrict__ arr, int b,
                                       float4& out)
{
    const float4* p = reinterpret_cast<const float4*>(arr + b);
    float4 a0 = p[0], a1 = p[1], a2 = p[2], a3 = p[3];
    float v[16] = { a0.x, a0.y, a0.z, a0.w, a1.x, a1.y, a1.z, a1.w,
                    a2.x, a2.y, a2.z, a2.w, a3.x, a3.y, a3.z, a3.w };
    float o0 = 0.f, o1 = 0.f, o2 = 0.f, o3 = 0.f;
#pragma unroll
    for (int k = 0; k < 11; k++) {
        float w = GW[k];
        o0 += w * v[k];
        o1 += w * v[k + 1];
        o2 += w * v[k + 2];
        o3 += w * v[k + 3];
    }
    out.x = o0; out.y = o1; out.z = o2; out.w = o3;
}

// Sliding-window vertical conv: 14 inputs (stride TS) -> 4 outputs.
__device__ __forceinline__ void vconv4(const float* __restrict__ arr, int b,
                                       float& o0, float& o1, float& o2, float& o3)
{
    float v[14];
#pragma unroll
    for (int j = 0; j < 14; j++) v[j] = arr[b + j * TS];
    o0 = 0.f; o1 = 0.f; o2 = 0.f; o3 = 0.f;
#pragma unroll
    for (int k = 0; k < 11; k++) {
        float w = GW[k];
        o0 += w * v[k];
        o1 += w * v[k + 1];
        o2 += w * v[k + 2];
        o3 += w * v[k + 3];
    }
}

__global__ __launch_bounds__(256) void ssim_l1_kernel(
    const float* __restrict__ pred, const float* __restrict__ tgt)
{
    extern __shared__ float sm[];
    float* sX  = sm;                   // IN*INS each
    float* sY  = sX  + IN * INS;
    float* sXX = sY  + IN * INS;
    float* sYY = sXX + IN * INS;
    float* sXY = sYY + IN * INS;
    float* hX  = sXY + IN * INS;       // IN*TS each (H-pass results)
    float* hY  = hX  + IN * TS;
    float* hXX = hY  + IN * TS;
    float* hYY = hXX + IN * TS;
    float* hXY = hYY + IN * TS;

    const int tid = threadIdx.x;
    const int plane = blockIdx.z;
    const float* __restrict__ px = pred + (size_t)plane * (IMH * IMW);
    const float* __restrict__ py = tgt  + (size_t)plane * (IMH * IMW);
    const int bx0 = blockIdx.x * TS - HALO;
    const int by0 = blockIdx.y * TS - HALO;

    // ---- Phase 1: load halo tile; products computed once; fold L1 for
    //      interior pixels (each image pixel is interior of exactly one tile).
    float l1 = 0.f;
    for (int i = tid; i < IN * IN; i += 256) {
        int r = i / IN;
        int c = i - r * IN;
        int gy = by0 + r, gx = bx0 + c;
        float x = 0.f, y = 0.f;
        if ((unsigned)gy < IMH && (unsigned)gx < IMW) {
            int o = gy * IMW + gx;
            x = px[o];
            y = py[o];
        }
        int s = r * INS + c;
        sX[s]  = x;      sY[s]  = y;
        sXX[s] = x * x;  sYY[s] = y * y;  sXY[s] = x * y;
        if (r >= HALO && r < IN - HALO && c >= HALO && c < IN - HALO)
            l1 += fabsf(x - y);
    }
    __syncthreads();

    // ---- Phase 2: horizontal pass. 42 rows x 8 groups of 4 cols = 336 items.
    //      Each item: 4x LDS.128 per array -> 4 outputs -> STS.128.
    for (int i = tid; i < IN * (TS / 4); i += 256) {
        int r  = i >> 3;
        int c0 = (i & 7) * 4;
        int b  = r * INS + c0;       // 16B-aligned: r*44, c0 both mult of 4
        int ho = r * TS + c0;        // 16B-aligned
        float4 o;
        hconv4(sX,  b, o); *reinterpret_cast<float4*>(hX  + ho) = o;
        hconv4(sY,  b, o); *reinterpret_cast<float4*>(hY  + ho) = o;
        hconv4(sXX, b, o); *reinterpret_cast<float4*>(hXX + ho) = o;
        hconv4(sYY, b, o); *reinterpret_cast<float4*>(hYY + ho) = o;
        hconv4(sXY, b, o); *reinterpret_cast<float4*>(hXY + ho) = o;
    }
    __syncthreads();

    // ---- Phase 3: vertical pass + SSIM. 32 cols x 8 row-groups (4 rows each)
    //      = exactly 256 threads. Warp lanes -> consecutive cols: conflict-free.
    float ssim = 0.f;
    {
        int c  = tid & 31;
        int r0 = (tid >> 5) * 4;
        int b  = r0 * TS + c;
        float mu1[4], mu2[4], ex2[4], ey2[4], exy[4];
        vconv4(hX,  b, mu1[0], mu1[1], mu1[2], mu1[3]);
        vconv4(hY,  b, mu2[0], mu2[1], mu2[2], mu2[3]);
        vconv4(hXX, b, ex2[0], ex2[1], ex2[2], ex2[3]);
        vconv4(hYY, b, ey2[0], ey2[1], ey2[2], ey2[3]);
        vconv4(hXY, b, exy[0], exy[1], exy[2], exy[3]);
#pragma unroll
        for (int j = 0; j < 4; j++) {
            float m11 = mu1[j] * mu1[j];
            float m22 = mu2[j] * mu2[j];
            float m12 = mu1[j] * mu2[j];
            float s1  = ex2[j] - m11;
            float s2  = ey2[j] - m22;
            float s12 = exy[j] - m12;
            const float C1 = 1e-4f;   // 0.01^2
            const float C2 = 9e-4f;   // 0.03^2
            float num = (2.f * m12 + C1) * (2.f * s12 + C2);
            float den = (m11 + m22 + C1) * (s1 + s2 + C2);
            ssim += __fdividef(num, den);
        }
    }

    // ---- Block reduction of (l1, ssim), then one atomicAdd pair per block.
#pragma unroll
    for (int off = 16; off > 0; off >>= 1) {
        l1   += __shfl_down_sync(0xffffffffu, l1,   off);
        ssim += __shfl_down_sync(0xffffffffu, ssim, off);
    }
    int warp = tid >> 5;
    int lane = tid & 31;
    __syncthreads();            // sX region must be dead before reuse
    if (lane == 0) {
        sX[warp]     = l1;
        sX[8 + warp] = ssim;
    }
    __syncthreads();
    if (tid == 0) {
        double a = 0.0, b = 0.0;
#pragma unroll
        for (int w = 0; w < 8; w++) { a += (double)sX[w]; b += (double)sX[8 + w]; }
        atomicAdd(&g_acc[0], a);
        atomicAdd(&g_acc[1], b);
    }
}

__global__ void finalize_kernel(float* __restrict__ out) {
    const double n = (double)NPIX;
    double l1 = g_acc[0] / n;
    double ss = g_acc[1] / n;
    out[0] = (float)(0.84 * l1 + (1.0 - 0.84) * (1.0 - ss));
}

extern "C" void kernel_launch(void* const* d_in, const int* in_sizes, int n_in,
                              void* d_out, int out_size)
{
    const float* pred = (const float*)d_in[0];
    const float* tgt  = (const float*)d_in[1];
    float* out = (float*)d_out;

    const int smem_bytes = (5 * IN * INS + 5 * IN * TS) * (int)sizeof(float); // 63840
    cudaFuncSetAttribute(ssim_l1_kernel,
                         cudaFuncAttributeMaxDynamicSharedMemorySize, smem_bytes);

    zero_acc_kernel<<<1, 1>>>();
    dim3 grid(IMW / TS, IMH / TS, NPLANES);   // 16 x 16 x 96
    ssim_l1_kernel<<<grid, 256, smem_bytes>>>(pred, tgt);
    finalize_kernel<<<1, 1>>>(out);
}

// round 5
// speedup vs baseline: 1.4618x; 1.2753x over previous
#include <cuda_runtime.h>

#define TS   32          // output tile (TS x TS)
#define HALO 5
#define IN   42          // TS + 2*HALO
#define INS  44          // padded smem row stride for input arrays (mult of 4)
#define IMH  512
#define IMW  512
#define NPLANES (32*3)
#define NPIX    ((long long)NPLANES * IMH * IMW)   // 25165824

// Normalized 11-tap Gaussian (sigma=1.5), compile-time so taps become FFMA-imm.
__device__ constexpr float GW[11] = {
    0.00102838f, 0.00759876f, 0.03600077f, 0.10936071f, 0.21300550f,
    0.26601172f,
    0.21300550f, 0.10936071f, 0.03600077f, 0.00759876f, 0.00102838f
};

// [0] = sum |x-y|, [1] = sum ssim_map. Zero-initialized at module load;
// finalize_kernel resets them after reading, so every replay starts from 0.
__device__ double g_acc[2] = {0.0, 0.0};

// Sliding-window horizontal conv: 16 inputs -> 4 outputs (cols j..j+3).
__device__ __forceinline__ void hconv4(const float* __restrict__ arr, int b,
                                       float4& out)
{
    const float4* p = reinterpret_cast<const float4*>(arr + b);
    float4 a0 = p[0], a1 = p[1], a2 = p[2], a3 = p[3];
    float v[16] = { a0.x, a0.y, a0.z, a0.w, a1.x, a1.y, a1.z, a1.w,
                    a2.x, a2.y, a2.z, a2.w, a3.x, a3.y, a3.z, a3.w };
    float o0 = 0.f, o1 = 0.f, o2 = 0.f, o3 = 0.f;
#pragma unroll
    for (int k = 0; k < 11; k++) {
        float w = GW[k];
        o0 += w * v[k];
        o1 += w * v[k + 1];
        o2 += w * v[k + 2];
        o3 += w * v[k + 3];
    }
    out.x = o0; out.y = o1; out.z = o2; out.w = o3;
}

// Sliding-window vertical conv: 18 inputs (stride TS) -> 8 outputs.
__device__ __forceinline__ void vconv8(const float* __restrict__ arr, int b,
                                       float* __restrict__ o)
{
    float v[18];
#pragma unroll
    for (int j = 0; j < 18; j++) v[j] = arr[b + j * TS];
#pragma unroll
    for (int m = 0; m < 8; m++) o[m] = 0.f;
#pragma unroll
    for (int k = 0; k < 11; k++) {
        float w = GW[k];
#pragma unroll
        for (int m = 0; m < 8; m++)
            o[m] += w * v[k + m];
    }
}

__global__ __launch_bounds__(256) void ssim_l1_kernel(
    const float* __restrict__ pred, const float* __restrict__ tgt)
{
    extern __shared__ float sm[];
    float* sX = sm;                   // IN*INS each
    float* sY = sX + IN * INS;
    float* sP = sY + IN * INS;        // x^2 + y^2
    float* sQ = sP + IN * INS;        // x*y
    float* hX = sQ + IN * INS;        // IN*TS each (H-pass results)
    float* hY = hX + IN * TS;
    float* hP = hY + IN * TS;
    float* hQ = hP + IN * TS;

    const int tid = threadIdx.x;
    const int plane = blockIdx.z;
    const float* __restrict__ px = pred + (size_t)plane * (IMH * IMW);
    const float* __restrict__ py = tgt  + (size_t)plane * (IMH * IMW);
    const int bx0 = blockIdx.x * TS - HALO;
    const int by0 = blockIdx.y * TS - HALO;

    // ---- Phase 1: load halo tile; products computed once; fold L1 for
    //      interior pixels (each image pixel is interior of exactly one tile).
    float l1 = 0.f;
    for (int i = tid; i < IN * IN; i += 256) {
        int r = i / IN;
        int c = i - r * IN;
        int gy = by0 + r, gx = bx0 + c;
        float x = 0.f, y = 0.f;
        if ((unsigned)gy < IMH && (unsigned)gx < IMW) {
            int o = gy * IMW + gx;
            x = px[o];
            y = py[o];
        }
        int s = r * INS + c;
        sX[s] = x;
        sY[s] = y;
        sP[s] = x * x + y * y;
        sQ[s] = x * y;
        if (r >= HALO && r < IN - HALO && c >= HALO && c < IN - HALO)
            l1 += fabsf(x - y);
    }
    __syncthreads();

    // ---- Phase 2: horizontal pass. 42 rows x 8 groups of 4 cols = 336 items.
    //      Each item: 4x LDS.128 per array -> 4 outputs -> STS.128.
    for (int i = tid; i < IN * (TS / 4); i += 256) {
        int r  = i >> 3;
        int c0 = (i & 7) * 4;
        int b  = r * INS + c0;       // 16B-aligned: r*44 and c0 mult of 4
        int ho = r * TS + c0;        // 16B-aligned
        float4 o;
        hconv4(sX, b, o); *reinterpret_cast<float4*>(hX + ho) = o;
        hconv4(sY, b, o); *reinterpret_cast<float4*>(hY + ho) = o;
        hconv4(sP, b, o); *reinterpret_cast<float4*>(hP + ho) = o;
        hconv4(sQ, b, o); *reinterpret_cast<float4*>(hQ + ho) = o;
    }
    __syncthreads();

    // ---- Phase 3: vertical pass + SSIM. 32 cols x 4 groups of 8 rows
    //      = 128 active threads. Warp lanes -> consecutive cols: conflict-free.
    float ssim = 0.f;
    if (tid < 128) {
        int c  = tid & 31;
        int r0 = (tid >> 5) * 8;
        int b  = r0 * TS + c;
        float mu1[8], mu2[8], ep[8], eq[8];
        vconv8(hX, b, mu1);
        vconv8(hY, b, mu2);
        vconv8(hP, b, ep);
        vconv8(hQ, b, eq);
#pragma unroll
        for (int j = 0; j < 8; j++) {
            float m11 = mu1[j] * mu1[j];
            float m22 = mu2[j] * mu2[j];
            float m12 = mu1[j] * mu2[j];
            float s12 = eq[j] - m12;          // sigma12
            float sss = ep[j] - m11 - m22;    // sigma1_sq + sigma2_sq
            const float C1 = 1e-4f;   // 0.01^2
            const float C2 = 9e-4f;   // 0.03^2
            float num = (2.f * m12 + C1) * (2.f * s12 + C2);
            float den = (m11 + m22 + C1) * (sss + C2);
            ssim += __fdividef(num, den);
        }
    }

    // ---- Block reduction of (l1, ssim), then one atomicAdd pair per block.
#pragma unroll
    for (int off = 16; off > 0; off >>= 1) {
        l1   += __shfl_down_sync(0xffffffffu, l1,   off);
        ssim += __shfl_down_sync(0xffffffffu, ssim, off);
    }
    int warp = tid >> 5;
    int lane = tid & 31;
    __syncthreads();            // sX region must be dead before reuse
    if (lane == 0) {
        sX[warp]     = l1;
        sX[8 + warp] = ssim;
    }
    __syncthreads();
    if (tid == 0) {
        double a = 0.0, b = 0.0;
#pragma unroll
        for (int w = 0; w < 8; w++) { a += (double)sX[w]; b += (double)sX[8 + w]; }
        atomicAdd(&g_acc[0], a);
        atomicAdd(&g_acc[1], b);
    }
}

__global__ void finalize_kernel(float* __restrict__ out) {
    const double n = (double)NPIX;
    double l1 = g_acc[0] / n;
    double ss = g_acc[1] / n;
    out[0] = (float)(0.84 * l1 + (1.0 - 0.84) * (1.0 - ss));
    g_acc[0] = 0.0;   // reset for the next replay (keeps launches deterministic)
    g_acc[1] = 0.0;
}

extern "C" void kernel_launch(void* const* d_in, const int* in_sizes, int n_in,
                              void* d_out, int out_size)
{
    const float* pred = (const float*)d_in[0];
    const float* tgt  = (const float*)d_in[1];
    float* out = (float*)d_out;

    const int smem_bytes = (4 * IN * INS + 4 * IN * TS) * (int)sizeof(float); // 51072
    cudaFuncSetAttribute(ssim_l1_kernel,
                         cudaFuncAttributeMaxDynamicSharedMemorySize, smem_bytes);

    dim3 grid(IMW / TS, IMH / TS, NPLANES);   // 16 x 16 x 96
    ssim_l1_kernel<<<grid, 256, smem_bytes>>>(pred, tgt);
    finalize_kernel<<<1, 1>>>(out);
}

// round 7
// speedup vs baseline: 1.7480x; 1.1957x over previous
#include <cuda_runtime.h>

#define TS   32          // output tile (TS x TS)
#define HALO 5
#define IN   42          // TS + 2*HALO
#define INS  44          // padded smem row stride for input arrays (mult of 4)
#define IMH  512
#define IMW  512
#define NPLANES (32*3)
#define NPIX    ((long long)NPLANES * IMH * IMW)   // 25165824

// Normalized 11-tap Gaussian (sigma=1.5), compile-time so taps become FFMA-imm.
__device__ constexpr float GW[11] = {
    0.00102838f, 0.00759876f, 0.03600077f, 0.10936071f, 0.21300550f,
    0.26601172f,
    0.21300550f, 0.10936071f, 0.03600077f, 0.00759876f, 0.00102838f
};

// [0] = sum |x-y|, [1] = sum ssim_map. Zero-initialized at module load;
// finalize_kernel resets them after reading, so every replay starts from 0.
__device__ double g_acc[2] = {0.0, 0.0};

// Sliding-window conv on a 16-value register window: outputs cols j..j+3.
__device__ __forceinline__ void conv16to4(const float* __restrict__ v, float4& out)
{
    float o0 = 0.f, o1 = 0.f, o2 = 0.f, o3 = 0.f;
#pragma unroll
    for (int k = 0; k < 11; k++) {
        float w = GW[k];
        o0 += w * v[k];
        o1 += w * v[k + 1];
        o2 += w * v[k + 2];
        o3 += w * v[k + 3];
    }
    out.x = o0; out.y = o1; out.z = o2; out.w = o3;
}

__global__ __launch_bounds__(256, 4) void ssim_l1_kernel(
    const float* __restrict__ pred, const float* __restrict__ tgt)
{
    extern __shared__ float sm[];
    float* sX = sm;                   // IN*INS each (raw inputs only)
    float* sY = sX + IN * INS;
    float* hX = sY + IN * INS;        // IN*TS each (H-pass results)
    float* hY = hX + IN * TS;
    float* hP = hY + IN * TS;         // H-conv of x^2+y^2
    float* hQ = hP + IN * TS;         // H-conv of x*y

    const int tid = threadIdx.x;
    const int plane = blockIdx.z;
    const float* __restrict__ px = pred + (size_t)plane * (IMH * IMW);
    const float* __restrict__ py = tgt  + (size_t)plane * (IMH * IMW);
    const int bx0 = blockIdx.x * TS - HALO;
    const int by0 = blockIdx.y * TS - HALO;

    // ---- Phase 1: load halo tile (x, y only); fold L1 for interior pixels
    //      (each image pixel is interior of exactly one tile).
    float l1 = 0.f;
    for (int i = tid; i < IN * IN; i += 256) {
        int r = i / IN;
        int c = i - r * IN;
        int gy = by0 + r, gx = bx0 + c;
        float x = 0.f, y = 0.f;
        if ((unsigned)gy < IMH && (unsigned)gx < IMW) {
            int o = gy * IMW + gx;
            x = px[o];
            y = py[o];
        }
        int s = r * INS + c;
        sX[s] = x;
        sY[s] = y;
        if (r >= HALO && r < IN - HALO && c >= HALO && c < IN - HALO)
            l1 += fabsf(x - y);
    }
    __syncthreads();

    // ---- Phase 2: horizontal pass, p/q derived in registers.
    //      42 rows x 8 groups of 4 cols = 336 items; 8x LDS.128 per item.
    for (int i = tid; i < IN * (TS / 4); i += 256) {
        int r  = i >> 3;
        int c0 = (i & 7) * 4;
        int b  = r * INS + c0;       // 16B-aligned: r*44 and c0 mult of 4
        int ho = r * TS + c0;        // 16B-aligned

        float xv[16], yv[16];
        {
            const float4* p4 = reinterpret_cast<const float4*>(sX + b);
#pragma unroll
            for (int j = 0; j < 4; j++) {
                float4 a = p4[j];
                xv[4*j] = a.x; xv[4*j+1] = a.y; xv[4*j+2] = a.z; xv[4*j+3] = a.w;
            }
            const float4* q4 = reinterpret_cast<const float4*>(sY + b);
#pragma unroll
            for (int j = 0; j < 4; j++) {
                float4 a = q4[j];
                yv[4*j] = a.x; yv[4*j+1] = a.y; yv[4*j+2] = a.z; yv[4*j+3] = a.w;
            }
        }
        float4 o;
        conv16to4(xv, o); *reinterpret_cast<float4*>(hX + ho) = o;
        conv16to4(yv, o); *reinterpret_cast<float4*>(hY + ho) = o;
        // overwrite windows in place: xv <- x^2+y^2, yv <- x*y
#pragma unroll
        for (int j = 0; j < 16; j++) {
            float x = xv[j], y = yv[j];
            float q = x * y;
            xv[j] = x * x + y * y;
            yv[j] = q;
        }
        conv16to4(xv, o); *reinterpret_cast<float4*>(hP + ho) = o;
        conv16to4(yv, o); *reinterpret_cast<float4*>(hQ + ho) = o;
    }
    __syncthreads();

    // ---- Phase 3: vertical pass (streaming scatter-accumulate) + SSIM.
    //      32 cols x 4 groups of 8 rows = 128 active threads; conflict-free.
    float ssim = 0.f;
    if (tid < 128) {
        int c  = tid & 31;
        int r0 = (tid >> 5) * 8;
        int b  = r0 * TS + c;

        float m1[8], m2[8], ep[8], eq[8];
#pragma unroll
        for (int m = 0; m < 8; m++) { m1[m] = 0.f; m2[m] = 0.f; ep[m] = 0.f; eq[m] = 0.f; }

#pragma unroll
        for (int j = 0; j < 18; j++) {
            int o = b + j * TS;
            float vx = hX[o];
            float vy = hY[o];
            float vp = hP[o];
            float vq = hQ[o];
#pragma unroll
            for (int m = 0; m < 8; m++) {
                int k = j - m;
                if (k >= 0 && k <= 10) {
                    float w = GW[k];
                    m1[m] += w * vx;
                    m2[m] += w * vy;
                    ep[m] += w * vp;
                    eq[m] += w * vq;
                }
            }
        }
#pragma unroll
        for (int j = 0; j < 8; j++) {
            float m11 = m1[j] * m1[j];
            float m22 = m2[j] * m2[j];
            float m12 = m1[j] * m2[j];
            float s12 = eq[j] - m12;          // sigma12
            float sss = ep[j] - m11 - m22;    // sigma1_sq + sigma2_sq
            const float C1 = 1e-4f;   // 0.01^2
            const float C2 = 9e-4f;   // 0.03^2
            float num = (2.f * m12 + C1) * (2.f * s12 + C2);
            float den = (m11 + m22 + C1) * (sss + C2);
            ssim += __fdividef(num, den);
        }
    }

    // ---- Block reduction of (l1, ssim), then one atomicAdd pair per block.
#pragma unroll
    for (int off = 16; off > 0; off >>= 1) {
        l1   += __shfl_down_sync(0xffffffffu, l1,   off);
        ssim += __shfl_down_sync(0xffffffffu, ssim, off);
    }
    int warp = tid >> 5;
    int lane = tid & 31;
    __syncthreads();            // sX region must be dead before reuse
    if (lane == 0) {
        sX[warp]     = l1;
        sX[8 + warp] = ssim;
    }
    __syncthreads();
    if (tid == 0) {
        double a = 0.0, b = 0.0;
#pragma unroll
        for (int w = 0; w < 8; w++) { a += (double)sX[w]; b += (double)sX[8 + w]; }
        atomicAdd(&g_acc[0], a);
        atomicAdd(&g_acc[1], b);
    }
}

__global__ void finalize_kernel(float* __restrict__ out) {
    const double n = (double)NPIX;
    double l1 = g_acc[0] / n;
    double ss = g_acc[1] / n;
    out[0] = (float)(0.84 * l1 + (1.0 - 0.84) * (1.0 - ss));
    g_acc[0] = 0.0;   // reset for the next replay (keeps launches deterministic)
    g_acc[1] = 0.0;
}

extern "C" void kernel_launch(void* const* d_in, const int* in_sizes, int n_in,
                              void* d_out, int out_size)
{
    const float* pred = (const float*)d_in[0];
    const float* tgt  = (const float*)d_in[1];
    float* out = (float*)d_out;

    const int smem_bytes = (2 * IN * INS + 4 * IN * TS) * (int)sizeof(float); // 36288
    cudaFuncSetAttribute(ssim_l1_kernel,
                         cudaFuncAttributeMaxDynamicSharedMemorySize, smem_bytes);

    dim3 grid(IMW / TS, IMH / TS, NPLANES);   // 16 x 16 x 96
    ssim_l1_kernel<<<grid, 256, smem_bytes>>>(pred, tgt);
    finalize_kernel<<<1, 1>>>(out);
}